// round 1
// baseline (speedup 1.0000x reference)
#include <cuda_runtime.h>
#include <cstdint>

// Problem constants
#define NB      8
#define NCH     3
#define IMG     1024
#define PATCH   128
#define DPOS    256          // 16x16 score grid
#define KSEL    16
#define NSAMP   500
#define HGRID   16
#define WGRID   16

// Persistent device scratch (no allocations allowed)
__device__ float d_snorm[NB][DPOS];
__device__ int   d_counts[NB][KSEL][DPOS];

// ---------------------------------------------------------------------------
// Threefry-2x32 (20 rounds), JAX partitionable layout:
//   bits[f] = o0 ^ o1 of E(key=(0,42), ctr=(hi=0, lo=f))
// ---------------------------------------------------------------------------
__device__ __forceinline__ uint32_t threefry_bits(uint32_t ctr) {
    const uint32_t K0 = 0u;
    const uint32_t K1 = 42u;
    const uint32_t K2 = 0x1BD11BDAu ^ K0 ^ K1;   // 0x1BD11BF0
    uint32_t x0 = K0;          // hi(ctr)=0 + ks0
    uint32_t x1 = ctr + K1;    // lo(ctr) + ks1
#define TFR(r) { x0 += x1; x1 = __funnelshift_l(x1, x1, (r)); x1 ^= x0; }
    TFR(13) TFR(15) TFR(26) TFR(6)
    x0 += K1; x1 += K2 + 1u;
    TFR(17) TFR(29) TFR(16) TFR(24)
    x0 += K2; x1 += K0 + 2u;
    TFR(13) TFR(15) TFR(26) TFR(6)
    x0 += K0; x1 += K1 + 3u;
    TFR(17) TFR(29) TFR(16) TFR(24)
    x0 += K1; x1 += K2 + 4u;
    TFR(13) TFR(15) TFR(26) TFR(6)
    x0 += K2; x1 += K0 + 5u;
#undef TFR
    return x0 ^ x1;
}

// jax.random.normal element at flat index f (float32 path)
__device__ __forceinline__ float jax_normal(uint32_t f) {
    uint32_t bits = threefry_bits(f);
    float fl = __uint_as_float((bits >> 9) | 0x3f800000u) - 1.0f;  // [0, 1)
    const float lo = -0.99999994f;                // nextafter(-1, 0)
    float u = fl * 2.0f + lo;                     // (hi-lo) rounds to exactly 2.0f
    u = fmaxf(lo, u);
    return __uint_as_float(0x3fb504f3u) * erfinvf(u);   // sqrt(2) * erfinv
}

// ---------------------------------------------------------------------------
// Kernel 1: normalize scores per batch, zero the count array
// grid = NB blocks, 256 threads
// ---------------------------------------------------------------------------
__global__ void prep_kernel(const float* __restrict__ scores) {
    int b = blockIdx.x, t = threadIdx.x;

    // zero counts: 8 blocks * 256 threads cover 8*16*256 ints, 16 each
    int gid = b * 256 + t;
    int* cp = &d_counts[0][0][0];
#pragma unroll
    for (int j = 0; j < 16; j++) cp[gid * 16 + j] = 0;

    float v = scores[b * DPOS + t];
    __shared__ float sh[64];
    float mn = v, mx = v;
#pragma unroll
    for (int off = 16; off; off >>= 1) {
        mn = fminf(mn, __shfl_down_sync(0xffffffffu, mn, off));
        mx = fmaxf(mx, __shfl_down_sync(0xffffffffu, mx, off));
    }
    int warp = t >> 5, lane = t & 31;
    if (lane == 0) { sh[warp] = mn; sh[32 + warp] = mx; }
    __syncthreads();
    if (t == 0) {
        float m0 = sh[0], m1 = sh[32];
#pragma unroll
        for (int j = 1; j < 8; j++) { m0 = fminf(m0, sh[j]); m1 = fmaxf(m1, sh[32 + j]); }
        sh[0] = m0; sh[32] = m1;
    }
    __syncthreads();
    mn = sh[0]; mx = sh[32];
    // match XLA: (s - smin) / (smax - smin + 1e-5), IEEE divide
    d_snorm[b][t] = __fdiv_rn(v - mn, (mx - mn) + 1e-5f);
}

// ---------------------------------------------------------------------------
// Kernel 2: perturbed top-K counting.
// grid = (125, NB), block = 128 (4 warps); one warp = one sample.
// Each lane owns 8 positions: pos = j*32 + lane.
// ---------------------------------------------------------------------------
__global__ void indicator_kernel() {
    __shared__ float s_sh[DPOS];
    int b = blockIdx.y;
    int t = threadIdx.x;
    int warp = t >> 5, lane = t & 31;

    s_sh[t]       = d_snorm[b][t];
    s_sh[t + 128] = d_snorm[b][t + 128];
    __syncthreads();

    int sample = blockIdx.x * 4 + warp;                 // 0..499
    uint32_t base = (uint32_t)((b * NSAMP + sample) * DPOS);

    float vals[8];
#pragma unroll
    for (int j = 0; j < 8; j++) {
        int pos = j * 32 + lane;
        float z = jax_normal(base + (uint32_t)pos);
        vals[j] = __fadd_rn(s_sh[pos], __fmul_rn(z, 0.05f));
    }

    int mysel = 0;
    for (int it = 0; it < KSEL; it++) {
        float bv = -1e30f; int bi = 1 << 30;
#pragma unroll
        for (int j = 0; j < 8; j++) {
            int pos = j * 32 + lane;
            if (vals[j] > bv || (vals[j] == bv && pos < bi)) { bv = vals[j]; bi = pos; }
        }
#pragma unroll
        for (int off = 16; off; off >>= 1) {
            float ov = __shfl_down_sync(0xffffffffu, bv, off);
            int   oi = __shfl_down_sync(0xffffffffu, bi, off);
            if (ov > bv || (ov == bv && oi < bi)) { bv = ov; bi = oi; }
        }
        bi = __shfl_sync(0xffffffffu, bi, 0);           // winner index (lowest on tie)
        int sel_j = bi >> 5;
        if (lane == (bi & 31)) {
#pragma unroll
            for (int j = 0; j < 8; j++) if (j == sel_j) vals[j] = -1e30f;
        }
        if (lane == it) mysel = bi;
    }

    // rank of my selected index among the 16 (ascending index = rank k)
    int rank = 0;
#pragma unroll
    for (int j = 0; j < KSEL; j++) {
        int oj = __shfl_sync(0xffffffffu, mysel, j);
        if (oj < mysel) rank++;
    }
    if (lane < KSEL) atomicAdd(&d_counts[b][rank][mysel], 1);
}

// ---------------------------------------------------------------------------
// Kernel 3: patch assembly.
// out[(b*16+k), c, p, q] = sum_{i,w} ind[b,k,i,w] * xpad[b,c,i*64+p, w*64+q]
// grid = (128 bk, 3 c, 4 ptile), block = 256; thread -> (q, 16 p-rows)
// ---------------------------------------------------------------------------
__global__ void __launch_bounds__(256) assemble_kernel(const float* __restrict__ x,
                                                       float* __restrict__ out) {
    __shared__ int   nz_idx[DPOS];
    __shared__ float nz_w[DPOS];
    __shared__ int   wcnt[8];

    int bk = blockIdx.x;
    int b = bk >> 4, k = bk & 15;
    int c = blockIdx.y;
    int pt = blockIdx.z;
    int t = threadIdx.x;
    int warp = t >> 5, lane = t & 31;

    // deterministic compaction of nonzero indicator entries (ascending pos)
    int cnt = d_counts[b][k][t];
    unsigned m = __ballot_sync(0xffffffffu, cnt > 0);
    if (lane == 0) wcnt[warp] = __popc(m);
    __syncthreads();
    int basec = 0, ntot = 0;
#pragma unroll
    for (int wj = 0; wj < 8; wj++) {
        int wc = wcnt[wj];
        if (wj < warp) basec += wc;
        ntot += wc;
    }
    if (cnt > 0) {
        int slot = basec + __popc(m & ((1u << lane) - 1u));
        nz_idx[slot] = t;
        nz_w[slot]   = __fdiv_rn((float)cnt, 500.0f);
    }
    __syncthreads();

    int q = t & 127;
    int ph = t >> 7;                 // 0..1
    int pbase = pt * 32 + ph * 16;

    float acc[16];
#pragma unroll
    for (int p = 0; p < 16; p++) acc[p] = 0.0f;

    const float* xb = x + ((size_t)(b * NCH + c) << 20);   // 1024*1024 per (b,c)

    for (int e = 0; e < ntot; e++) {
        int pos  = nz_idx[e];
        float wt = nz_w[e];
        int iw = pos & 15;           // w grid
        int ii = pos >> 4;           // i grid
        int col = iw * 64 + q - 32;
        if ((unsigned)col < 1024u) {
            int row0 = ii * 64 + pbase - 32;
            const float* xr = xb + col;
#pragma unroll
            for (int p = 0; p < 16; p++) {
                int row = row0 + p;
                if ((unsigned)row < 1024u)
                    acc[p] = fmaf(wt, __ldg(xr + ((size_t)row << 10)), acc[p]);
            }
        }
    }

    float* op = out + ((size_t)(bk * NCH + c) << 14) + (size_t)pbase * PATCH + q;
#pragma unroll
    for (int p = 0; p < 16; p++) op[p * PATCH] = acc[p];
}

// ---------------------------------------------------------------------------
extern "C" void kernel_launch(void* const* d_in, const int* in_sizes, int n_in,
                              void* d_out, int out_size) {
    const float* x      = (const float*)d_in[0];
    const float* scores = (const float*)d_in[1];
    // robustness: identify by size (x_high = 25165824 elems, scores = 2048)
    if (n_in >= 2 && in_sizes[0] == NB * HGRID * WGRID) {
        const float* tmp = x; x = scores; scores = tmp;
    }
    float* out = (float*)d_out;

    prep_kernel<<<NB, 256>>>(scores);
    indicator_kernel<<<dim3(125, NB), 128>>>();
    assemble_kernel<<<dim3(NB * KSEL, NCH, 4), 256>>>(x, out);
}

// round 2
// speedup vs baseline: 1.5607x; 1.5607x over previous
#include <cuda_runtime.h>
#include <cstdint>

#define NB      8
#define NCH     3
#define IMG     1024
#define PATCH   128
#define DPOS    256
#define KSEL    16
#define NSAMP   500
#define HGRID   16
#define WGRID   16

// Persistent device scratch (zero-initialized at module load; build_kernel
// restores d_counts to zero after consuming it, so every graph replay starts
// from a clean state).
__device__ int   d_counts[NB][KSEL][DPOS];
__device__ int   d_nentry[NB];
__device__ int   d_epos[NB][DPOS];
__device__ float d_ewt[NB][DPOS][KSEL];

// ---------------------------------------------------------------------------
// Threefry-2x32 (20 rounds), JAX partitionable layout:
//   bits[f] = o0 ^ o1 of E(key=(0,42), ctr=(hi=0, lo=f))
// ---------------------------------------------------------------------------
__device__ __forceinline__ uint32_t threefry_bits(uint32_t ctr) {
    const uint32_t K0 = 0u;
    const uint32_t K1 = 42u;
    const uint32_t K2 = 0x1BD11BDAu ^ K0 ^ K1;
    uint32_t x0 = K0;
    uint32_t x1 = ctr + K1;
#define TFR(r) { x0 += x1; x1 = __funnelshift_l(x1, x1, (r)); x1 ^= x0; }
    TFR(13) TFR(15) TFR(26) TFR(6)
    x0 += K1; x1 += K2 + 1u;
    TFR(17) TFR(29) TFR(16) TFR(24)
    x0 += K2; x1 += K0 + 2u;
    TFR(13) TFR(15) TFR(26) TFR(6)
    x0 += K0; x1 += K1 + 3u;
    TFR(17) TFR(29) TFR(16) TFR(24)
    x0 += K1; x1 += K2 + 4u;
    TFR(13) TFR(15) TFR(26) TFR(6)
    x0 += K2; x1 += K0 + 5u;
#undef TFR
    return x0 ^ x1;
}

__device__ __forceinline__ float jax_normal(uint32_t f) {
    uint32_t bits = threefry_bits(f);
    float fl = __uint_as_float((bits >> 9) | 0x3f800000u) - 1.0f;  // [0,1)
    const float lo = -0.99999994f;
    float u = fl * 2.0f + lo;
    u = fmaxf(lo, u);
    return __uint_as_float(0x3fb504f3u) * erfinvf(u);   // sqrt(2)*erfinv
}

// ---------------------------------------------------------------------------
// Kernel 1: perturbed top-K counting with fused score normalization.
// grid = (125, NB), block = 128 (4 warps); one warp = one sample.
// ---------------------------------------------------------------------------
__global__ void indicator_kernel(const float* __restrict__ scores) {
    __shared__ float s_sh[DPOS];
    __shared__ float red[64];
    int b = blockIdx.y;
    int t = threadIdx.x;
    int warp = t >> 5, lane = t & 31;

    // fused normalization (redundant per block; trivial cost)
    float v0 = __ldg(scores + b * DPOS + t);
    float v1 = __ldg(scores + b * DPOS + 128 + t);
    float mn = fminf(v0, v1), mx = fmaxf(v0, v1);
#pragma unroll
    for (int off = 16; off; off >>= 1) {
        mn = fminf(mn, __shfl_down_sync(0xffffffffu, mn, off));
        mx = fmaxf(mx, __shfl_down_sync(0xffffffffu, mx, off));
    }
    if (lane == 0) { red[warp] = mn; red[32 + warp] = mx; }
    __syncthreads();
    if (t == 0) {
        float m0 = red[0], m1 = red[32];
#pragma unroll
        for (int j = 1; j < 4; j++) { m0 = fminf(m0, red[j]); m1 = fmaxf(m1, red[32 + j]); }
        red[0] = m0; red[32] = m1;
    }
    __syncthreads();
    mn = red[0]; mx = red[32];
    float den = (mx - mn) + 1e-5f;
    s_sh[t]       = __fdiv_rn(v0 - mn, den);
    s_sh[t + 128] = __fdiv_rn(v1 - mn, den);
    __syncthreads();

    int sample = blockIdx.x * 4 + warp;                 // 0..499
    uint32_t base = (uint32_t)((b * NSAMP + sample) * DPOS);

    float vals[8];
#pragma unroll
    for (int j = 0; j < 8; j++) {
        int pos = j * 32 + lane;
        float z = jax_normal(base + (uint32_t)pos);
        vals[j] = __fadd_rn(s_sh[pos], __fmul_rn(z, 0.05f));
    }

    int mysel = 0;
    for (int it = 0; it < KSEL; it++) {
        float bv = -1e30f; int bi = 1 << 30;
#pragma unroll
        for (int j = 0; j < 8; j++) {
            int pos = j * 32 + lane;
            if (vals[j] > bv || (vals[j] == bv && pos < bi)) { bv = vals[j]; bi = pos; }
        }
#pragma unroll
        for (int off = 16; off; off >>= 1) {
            float ov = __shfl_down_sync(0xffffffffu, bv, off);
            int   oi = __shfl_down_sync(0xffffffffu, bi, off);
            if (ov > bv || (ov == bv && oi < bi)) { bv = ov; bi = oi; }
        }
        bi = __shfl_sync(0xffffffffu, bi, 0);           // winner (lowest idx on tie)
        int sel_j = bi >> 5;
        if (lane == (bi & 31)) {
#pragma unroll
            for (int j = 0; j < 8; j++) if (j == sel_j) vals[j] = -1e30f;
        }
        if (lane == it) mysel = bi;
    }

    int rank = 0;
#pragma unroll
    for (int j = 0; j < KSEL; j++) {
        int oj = __shfl_sync(0xffffffffu, mysel, j);
        if (oj < mysel) rank++;
    }
    if (lane < KSEL) atomicAdd(&d_counts[b][rank][mysel], 1);
}

// ---------------------------------------------------------------------------
// Kernel 2: build per-batch union position list with dense k-weight vectors.
// Also restores d_counts to zero (invariant for graph replay).
// grid = NB, block = 256 (thread = position)
// ---------------------------------------------------------------------------
__global__ void build_kernel() {
    __shared__ int wcnt[8];
    int b = blockIdx.x, t = threadIdx.x;
    int warp = t >> 5, lane = t & 31;

    int cnt[KSEL]; int any = 0;
#pragma unroll
    for (int k = 0; k < KSEL; k++) {
        cnt[k] = d_counts[b][k][t];
        any |= cnt[k];
        d_counts[b][k][t] = 0;
    }
    unsigned m = __ballot_sync(0xffffffffu, any != 0);
    if (lane == 0) wcnt[warp] = __popc(m);
    __syncthreads();
    int basec = 0, ntot = 0;
#pragma unroll
    for (int wj = 0; wj < 8; wj++) {
        int wc = wcnt[wj];
        if (wj < warp) basec += wc;
        ntot += wc;
    }
    if (any) {
        int slot = basec + __popc(m & ((1u << lane) - 1u));
        d_epos[b][slot] = t;
#pragma unroll
        for (int k = 0; k < KSEL; k++)
            d_ewt[b][slot][k] = __fdiv_rn((float)cnt[k], 500.0f);
    }
    if (t == 0) d_nentry[b] = ntot;
}

// ---------------------------------------------------------------------------
// Kernel 3: patch assembly, all 16 k fused per block (union-list dedup).
// grid = (64 row-pairs, 3 c, 8 b), block = 256: thread = (q=t&127, ph=t>>7)
// out[(b*16+k), c, p, q] = sum_e wt[e][k] * xpad[b,c, ii*64+p-32, iw*64+q-32]
// ---------------------------------------------------------------------------
__global__ void __launch_bounds__(256) assemble_kernel(const float* __restrict__ x,
                                                       float* __restrict__ out) {
    __shared__ int   s_pos[DPOS];
    __shared__ float s_wt[DPOS][KSEL];

    int pt = blockIdx.x;          // 0..63 (pairs of output rows)
    int c  = blockIdx.y;
    int b  = blockIdx.z;
    int t  = threadIdx.x;

    int nE = d_nentry[b];
    if (t < nE) {
        s_pos[t] = d_epos[b][t];
#pragma unroll
        for (int k = 0; k < KSEL; k++) s_wt[t][k] = d_ewt[b][t][k];
    }
    __syncthreads();

    int q  = t & 127;
    int ph = t >> 7;
    int p  = pt * 2 + ph;

    float acc[KSEL];
#pragma unroll
    for (int k = 0; k < KSEL; k++) acc[k] = 0.0f;

    const float* xb = x + ((size_t)(b * NCH + c) << 20);

    int e = 0;
    // software-pipelined by 2 for load/FMA overlap
    for (; e + 2 <= nE; e += 2) {
        int pos0 = s_pos[e],     pos1 = s_pos[e + 1];
        int col0 = (pos0 & 15) * 64 + q - 32, row0 = (pos0 >> 4) * 64 + p - 32;
        int col1 = (pos1 & 15) * 64 + q - 32, row1 = (pos1 >> 4) * 64 + p - 32;
        float v0 = 0.0f, v1 = 0.0f;
        if ((unsigned)col0 < 1024u && (unsigned)row0 < 1024u)
            v0 = __ldg(xb + ((size_t)row0 << 10) + col0);
        if ((unsigned)col1 < 1024u && (unsigned)row1 < 1024u)
            v1 = __ldg(xb + ((size_t)row1 << 10) + col1);
#pragma unroll
        for (int k = 0; k < KSEL; k++) acc[k] = fmaf(s_wt[e][k], v0, acc[k]);
#pragma unroll
        for (int k = 0; k < KSEL; k++) acc[k] = fmaf(s_wt[e + 1][k], v1, acc[k]);
    }
    for (; e < nE; e++) {
        int pos = s_pos[e];
        int col = (pos & 15) * 64 + q - 32, row = (pos >> 4) * 64 + p - 32;
        float v = 0.0f;
        if ((unsigned)col < 1024u && (unsigned)row < 1024u)
            v = __ldg(xb + ((size_t)row << 10) + col);
#pragma unroll
        for (int k = 0; k < KSEL; k++) acc[k] = fmaf(s_wt[e][k], v, acc[k]);
    }

#pragma unroll
    for (int k = 0; k < KSEL; k++) {
        float* op = out + (((size_t)((b * KSEL + k) * NCH + c)) << 14)
                        + ((size_t)p << 7) + q;
        *op = acc[k];
    }
}

// ---------------------------------------------------------------------------
extern "C" void kernel_launch(void* const* d_in, const int* in_sizes, int n_in,
                              void* d_out, int out_size) {
    const float* x      = (const float*)d_in[0];
    const float* scores = (const float*)d_in[1];
    if (n_in >= 2 && in_sizes[0] == NB * HGRID * WGRID) {
        const float* tmp = x; x = scores; scores = tmp;
    }
    float* out = (float*)d_out;

    indicator_kernel<<<dim3(125, NB), 128>>>(scores);
    build_kernel<<<NB, 256>>>();
    assemble_kernel<<<dim3(64, NCH, NB), 256>>>(x, out);
}

// round 3
// speedup vs baseline: 1.8376x; 1.1775x over previous
#include <cuda_runtime.h>
#include <cstdint>

#define NB      8
#define NCH     3
#define IMG     1024
#define PATCH   128
#define DPOS    256
#define KSEL    16
#define NSAMP   500
#define HGRID   16
#define WGRID   16

typedef unsigned long long ull;

// Persistent device scratch (zero-init at load; build_kernel re-zeroes
// d_counts after consuming it -> clean state for every graph replay).
__device__ int  d_counts[NB][KSEL][DPOS];
__device__ int  d_nentry[NB];
__device__ int  d_epos[NB][DPOS];
__device__ ull  d_ewt2[NB][DPOS][KSEL];   // packed {w,w} f32x2 weights

// ---------------------------------------------------------------------------
// Threefry-2x32 (20 rounds), JAX partitionable layout:
//   bits[f] = o0 ^ o1 of E(key=(0,42), ctr=(hi=0, lo=f))
// ---------------------------------------------------------------------------
__device__ __forceinline__ uint32_t threefry_bits(uint32_t ctr) {
    const uint32_t K0 = 0u;
    const uint32_t K1 = 42u;
    const uint32_t K2 = 0x1BD11BDAu ^ K0 ^ K1;
    uint32_t x0 = K0;
    uint32_t x1 = ctr + K1;
#define TFR(r) { x0 += x1; x1 = __funnelshift_l(x1, x1, (r)); x1 ^= x0; }
    TFR(13) TFR(15) TFR(26) TFR(6)
    x0 += K1; x1 += K2 + 1u;
    TFR(17) TFR(29) TFR(16) TFR(24)
    x0 += K2; x1 += K0 + 2u;
    TFR(13) TFR(15) TFR(26) TFR(6)
    x0 += K0; x1 += K1 + 3u;
    TFR(17) TFR(29) TFR(16) TFR(24)
    x0 += K1; x1 += K2 + 4u;
    TFR(13) TFR(15) TFR(26) TFR(6)
    x0 += K2; x1 += K0 + 5u;
#undef TFR
    return x0 ^ x1;
}

__device__ __forceinline__ float jax_normal(uint32_t f) {
    uint32_t bits = threefry_bits(f);
    float fl = __uint_as_float((bits >> 9) | 0x3f800000u) - 1.0f;  // [0,1)
    const float lo = -0.99999994f;
    float u = fl * 2.0f + lo;
    u = fmaxf(lo, u);
    return __uint_as_float(0x3fb504f3u) * erfinvf(u);   // sqrt(2)*erfinv
}

// monotone float -> sortable u32 (strictly order-preserving)
__device__ __forceinline__ uint32_t fkey(float v) {
    uint32_t u = __float_as_uint(v);
    return u ^ (uint32_t)(((int)u >> 31) | 0x80000000);
}

// ---------------------------------------------------------------------------
// Kernel 1: perturbed top-K counting; fused normalization; 2 samples/warp.
// grid = (63, NB), block = 128 (4 warps); warp w -> samples 2*(bx*4+w)+{0,1}
// ---------------------------------------------------------------------------
__global__ void indicator_kernel(const float* __restrict__ scores) {
    __shared__ float s_sh[DPOS];
    __shared__ float red[64];
    int b = blockIdx.y;
    int t = threadIdx.x;
    int warp = t >> 5, lane = t & 31;

    // per-batch min/max normalize (redundant per block; trivial)
    float v0 = __ldg(scores + b * DPOS + t);
    float v1 = __ldg(scores + b * DPOS + 128 + t);
    float mn = fminf(v0, v1), mx = fmaxf(v0, v1);
#pragma unroll
    for (int off = 16; off; off >>= 1) {
        mn = fminf(mn, __shfl_down_sync(0xffffffffu, mn, off));
        mx = fmaxf(mx, __shfl_down_sync(0xffffffffu, mx, off));
    }
    if (lane == 0) { red[warp] = mn; red[32 + warp] = mx; }
    __syncthreads();
    if (t == 0) {
        float m0 = red[0], m1 = red[32];
#pragma unroll
        for (int j = 1; j < 4; j++) { m0 = fminf(m0, red[j]); m1 = fmaxf(m1, red[32 + j]); }
        red[0] = m0; red[32] = m1;
    }
    __syncthreads();
    mn = red[0]; mx = red[32];
    float den = (mx - mn) + 1e-5f;
    s_sh[t]       = __fdiv_rn(v0 - mn, den);
    s_sh[t + 128] = __fdiv_rn(v1 - mn, den);
    __syncthreads();

    int sA = (blockIdx.x * 4 + warp) * 2;
    int sB = sA + 1;
    bool validA = sA < NSAMP, validB = sB < NSAMP;
    uint32_t baseA = (uint32_t)((b * NSAMP + sA) * DPOS);
    uint32_t baseB = baseA + DPOS;

    uint32_t ka[8], kb[8];
#pragma unroll
    for (int j = 0; j < 8; j++) {
        int pos = j * 32 + lane;
        float za = jax_normal(baseA + (uint32_t)pos);
        float zb = jax_normal(baseB + (uint32_t)pos);
        ka[j] = fkey(__fadd_rn(s_sh[pos], __fmul_rn(za, 0.05f)));
        kb[j] = fkey(__fadd_rn(s_sh[pos], __fmul_rn(zb, 0.05f)));
    }

    int selA = 0, selB = 0;
    for (int it = 0; it < KSEL; it++) {
        uint32_t bkA = 0u, bkB = 0u;
        int bpA = 0x7fffffff, bpB = 0x7fffffff;
#pragma unroll
        for (int j = 0; j < 8; j++) {
            int pos = j * 32 + lane;
            if (ka[j] > bkA) { bkA = ka[j]; bpA = pos; }
            if (kb[j] > bkB) { bkB = kb[j]; bpB = pos; }
        }
        uint32_t mA = __reduce_max_sync(0xffffffffu, bkA);
        uint32_t mB = __reduce_max_sync(0xffffffffu, bkB);
        unsigned cA = (bkA == mA) ? (unsigned)bpA : 0x7fffffffu;
        unsigned cB = (bkB == mB) ? (unsigned)bpB : 0x7fffffffu;
        int wA = (int)__reduce_min_sync(0xffffffffu, cA);
        int wB = (int)__reduce_min_sync(0xffffffffu, cB);
        int sjA = wA >> 5, sjB = wB >> 5;
        if (lane == (wA & 31)) {
#pragma unroll
            for (int j = 0; j < 8; j++) if (j == sjA) ka[j] = 0u;
        }
        if (lane == (wB & 31)) {
#pragma unroll
            for (int j = 0; j < 8; j++) if (j == sjB) kb[j] = 0u;
        }
        if (lane == it) { selA = wA; selB = wB; }
    }

    // rank = index order among the 16 selections
    int rA = 0, rB = 0;
#pragma unroll
    for (int j = 0; j < KSEL; j++) {
        int oA = __shfl_sync(0xffffffffu, selA, j);
        int oB = __shfl_sync(0xffffffffu, selB, j);
        if (oA < selA) rA++;
        if (oB < selB) rB++;
    }
    if (lane < KSEL) {
        if (validA) atomicAdd(&d_counts[b][rA][selA], 1);
        if (validB) atomicAdd(&d_counts[b][rB][selB], 1);
    }
}

// ---------------------------------------------------------------------------
// Kernel 2: build per-batch union position list + packed f32x2 weights.
// Restores d_counts to zero. grid = NB, block = 256 (thread = position)
// ---------------------------------------------------------------------------
__global__ void build_kernel() {
    __shared__ int wcnt[8];
    int b = blockIdx.x, t = threadIdx.x;
    int warp = t >> 5, lane = t & 31;

    int cnt[KSEL]; int any = 0;
#pragma unroll
    for (int k = 0; k < KSEL; k++) {
        cnt[k] = d_counts[b][k][t];
        any |= cnt[k];
        d_counts[b][k][t] = 0;
    }
    unsigned m = __ballot_sync(0xffffffffu, any != 0);
    if (lane == 0) wcnt[warp] = __popc(m);
    __syncthreads();
    int basec = 0, ntot = 0;
#pragma unroll
    for (int wj = 0; wj < 8; wj++) {
        int wc = wcnt[wj];
        if (wj < warp) basec += wc;
        ntot += wc;
    }
    if (any) {
        int slot = basec + __popc(m & ((1u << lane) - 1u));
        d_epos[b][slot] = t;
#pragma unroll
        for (int k = 0; k < KSEL; k++) {
            float w = __fdiv_rn((float)cnt[k], 500.0f);
            uint32_t wb = __float_as_uint(w);
            d_ewt2[b][slot][k] = ((ull)wb << 32) | (ull)wb;
        }
    }
    if (t == 0) d_nentry[b] = ntot;
}

// ---------------------------------------------------------------------------
// Kernel 3: patch assembly, 16 k fused, q-pairs packed via fma.rn.f32x2.
// grid = (32 ptile, 3 c, 8 b), block = 256: qt = t&63 (q pair), pr = t>>6.
// Window columns are always even => each q-pair shares one bounds predicate
// and one LDG.64.
// ---------------------------------------------------------------------------
__device__ __forceinline__ ull fma2(ull a, ull b, ull c) {
    ull d;
    asm("fma.rn.f32x2 %0, %1, %2, %3;" : "=l"(d) : "l"(a), "l"(b), "l"(c));
    return d;
}

__global__ void __launch_bounds__(256) assemble_kernel(const float* __restrict__ x,
                                                       float* __restrict__ out) {
    __shared__ int s_pos[DPOS];
    __shared__ ull s_wt2[DPOS][KSEL];

    int pt = blockIdx.x;          // 0..31 (4 output rows each)
    int c  = blockIdx.y;
    int b  = blockIdx.z;
    int t  = threadIdx.x;

    int nE = d_nentry[b];
    if (t < nE) {
        s_pos[t] = d_epos[b][t];
#pragma unroll
        for (int k = 0; k < KSEL; k++) s_wt2[t][k] = d_ewt2[b][t][k];
    }
    __syncthreads();

    int qt = t & 63;              // q pair: q = 2qt, 2qt+1
    int pr = t >> 6;              // 0..3
    int p  = pt * 4 + pr;
    int qc = 2 * qt - 32;         // column offset (always even)
    int pc = p - 32;

    ull acc[KSEL];
#pragma unroll
    for (int k = 0; k < KSEL; k++) acc[k] = 0ull;

    const float* xb = x + ((size_t)(b * NCH + c) << 20);

    int e = 0;
    for (; e + 2 <= nE; e += 2) {
        int pos0 = s_pos[e], pos1 = s_pos[e + 1];
        int col0 = (pos0 & 15) * 64 + qc, row0 = (pos0 >> 4) * 64 + pc;
        int col1 = (pos1 & 15) * 64 + qc, row1 = (pos1 >> 4) * 64 + pc;
        ull v0 = 0ull, v1 = 0ull;
        if ((unsigned)col0 < 1024u && (unsigned)row0 < 1024u)
            v0 = *(const ull*)(xb + ((size_t)row0 << 10) + col0);
        if ((unsigned)col1 < 1024u && (unsigned)row1 < 1024u)
            v1 = *(const ull*)(xb + ((size_t)row1 << 10) + col1);
#pragma unroll
        for (int k = 0; k < KSEL; k++) acc[k] = fma2(s_wt2[e][k], v0, acc[k]);
#pragma unroll
        for (int k = 0; k < KSEL; k++) acc[k] = fma2(s_wt2[e + 1][k], v1, acc[k]);
    }
    for (; e < nE; e++) {
        int pos = s_pos[e];
        int col = (pos & 15) * 64 + qc, row = (pos >> 4) * 64 + pc;
        ull v = 0ull;
        if ((unsigned)col < 1024u && (unsigned)row < 1024u)
            v = *(const ull*)(xb + ((size_t)row << 10) + col);
#pragma unroll
        for (int k = 0; k < KSEL; k++) acc[k] = fma2(s_wt2[e][k], v, acc[k]);
    }

#pragma unroll
    for (int k = 0; k < KSEL; k++) {
        ull* op = (ull*)(out + (((size_t)((b * KSEL + k) * NCH + c)) << 14)
                             + ((size_t)p << 7) + 2 * qt);
        *op = acc[k];
    }
}

// ---------------------------------------------------------------------------
extern "C" void kernel_launch(void* const* d_in, const int* in_sizes, int n_in,
                              void* d_out, int out_size) {
    const float* x      = (const float*)d_in[0];
    const float* scores = (const float*)d_in[1];
    if (n_in >= 2 && in_sizes[0] == NB * HGRID * WGRID) {
        const float* tmp = x; x = scores; scores = tmp;
    }
    float* out = (float*)d_out;

    indicator_kernel<<<dim3(63, NB), 128>>>(scores);
    build_kernel<<<NB, 256>>>();
    assemble_kernel<<<dim3(32, NCH, NB), 256>>>(x, out);
}

// round 5
// speedup vs baseline: 2.1259x; 1.1569x over previous
#include <cuda_runtime.h>
#include <cstdint>

#define NB      8
#define NCH     3
#define IMG     1024
#define PATCH   128
#define DPOS    256
#define KSEL    16
#define NSAMP   500
#define HGRID   16
#define WGRID   16

typedef unsigned long long ull;

// Persistent device scratch (zero-init at load; build_kernel re-zeroes
// d_counts after consuming it -> clean state for every graph replay).
__device__ int  d_counts[NB][KSEL][DPOS];
__device__ int  d_nentry[NB];
__device__ int  d_epos[NB][DPOS];
__device__ __align__(16) ull d_ewt2[NB][DPOS][KSEL];   // packed {w,w} f32x2

// ---------------------------------------------------------------------------
// Threefry-2x32 (20 rounds), JAX partitionable layout:
//   bits[f] = o0 ^ o1 of E(key=(0,42), ctr=(hi=0, lo=f))
// ---------------------------------------------------------------------------
__device__ __forceinline__ uint32_t threefry_bits(uint32_t ctr) {
    const uint32_t K0 = 0u;
    const uint32_t K1 = 42u;
    const uint32_t K2 = 0x1BD11BDAu ^ K0 ^ K1;
    uint32_t x0 = K0;
    uint32_t x1 = ctr + K1;
#define TFR(r) { x0 += x1; x1 = __funnelshift_l(x1, x1, (r)); x1 ^= x0; }
    TFR(13) TFR(15) TFR(26) TFR(6)
    x0 += K1; x1 += K2 + 1u;
    TFR(17) TFR(29) TFR(16) TFR(24)
    x0 += K2; x1 += K0 + 2u;
    TFR(13) TFR(15) TFR(26) TFR(6)
    x0 += K0; x1 += K1 + 3u;
    TFR(17) TFR(29) TFR(16) TFR(24)
    x0 += K1; x1 += K2 + 4u;
    TFR(13) TFR(15) TFR(26) TFR(6)
    x0 += K2; x1 += K0 + 5u;
#undef TFR
    return x0 ^ x1;
}

__device__ __forceinline__ float jax_normal(uint32_t f) {
    uint32_t bits = threefry_bits(f);
    float fl = __uint_as_float((bits >> 9) | 0x3f800000u) - 1.0f;  // [0,1)
    const float lo = -0.99999994f;
    float u = fl * 2.0f + lo;
    u = fmaxf(lo, u);
    return __uint_as_float(0x3fb504f3u) * erfinvf(u);   // sqrt(2)*erfinv
}

// monotone float -> sortable u32 (strictly order-preserving)
__device__ __forceinline__ uint32_t fkey(float v) {
    uint32_t u = __float_as_uint(v);
    return u ^ (uint32_t)(((int)u >> 31) | 0x80000000);
}

// ---------------------------------------------------------------------------
// Kernel 1: perturbed top-K counting; fused normalization; 1 sample/warp,
// REDUX-based selection. grid = (125, NB), block = 128 (4 warps).
// ---------------------------------------------------------------------------
__global__ void indicator_kernel(const float* __restrict__ scores) {
    __shared__ float s_sh[DPOS];
    __shared__ float red[64];
    int b = blockIdx.y;
    int t = threadIdx.x;
    int warp = t >> 5, lane = t & 31;

    // per-batch min/max normalize (redundant per block; trivial)
    float v0 = __ldg(scores + b * DPOS + t);
    float v1 = __ldg(scores + b * DPOS + 128 + t);
    float mn = fminf(v0, v1), mx = fmaxf(v0, v1);
#pragma unroll
    for (int off = 16; off; off >>= 1) {
        mn = fminf(mn, __shfl_down_sync(0xffffffffu, mn, off));
        mx = fmaxf(mx, __shfl_down_sync(0xffffffffu, mx, off));
    }
    if (lane == 0) { red[warp] = mn; red[32 + warp] = mx; }
    __syncthreads();
    if (t == 0) {
        float m0 = red[0], m1 = red[32];
#pragma unroll
        for (int j = 1; j < 4; j++) { m0 = fminf(m0, red[j]); m1 = fmaxf(m1, red[32 + j]); }
        red[0] = m0; red[32] = m1;
    }
    __syncthreads();
    mn = red[0]; mx = red[32];
    float den = (mx - mn) + 1e-5f;
    s_sh[t]       = __fdiv_rn(v0 - mn, den);
    s_sh[t + 128] = __fdiv_rn(v1 - mn, den);
    __syncthreads();

    int sample = blockIdx.x * 4 + warp;            // 0..499
    uint32_t base = (uint32_t)((b * NSAMP + sample) * DPOS);

    uint32_t ka[8];
#pragma unroll
    for (int j = 0; j < 8; j++) {
        int pos = j * 32 + lane;
        float z = jax_normal(base + (uint32_t)pos);
        ka[j] = fkey(__fadd_rn(s_sh[pos], __fmul_rn(z, 0.05f)));
    }

    int sel = 0;
    for (int it = 0; it < KSEL; it++) {
        uint32_t bk = 0u;
        int bp = 0x7fffffff;
#pragma unroll
        for (int j = 0; j < 8; j++) {
            int pos = j * 32 + lane;
            if (ka[j] > bk) { bk = ka[j]; bp = pos; }
        }
        uint32_t m = __reduce_max_sync(0xffffffffu, bk);
        unsigned cand = (bk == m) ? (unsigned)bp : 0x7fffffffu;
        int w = (int)__reduce_min_sync(0xffffffffu, cand);
        int sj = w >> 5;
        if (lane == (w & 31)) {
#pragma unroll
            for (int j = 0; j < 8; j++) if (j == sj) ka[j] = 0u;
        }
        if (lane == it) sel = w;
    }

    // rank = index order among the 16 selections
    int r = 0;
#pragma unroll
    for (int j = 0; j < KSEL; j++) {
        int o = __shfl_sync(0xffffffffu, sel, j);
        if (o < sel) r++;
    }
    if (lane < KSEL) atomicAdd(&d_counts[b][r][sel], 1);
}

// ---------------------------------------------------------------------------
// Kernel 2: build per-batch union position list + packed f32x2 weights.
// Restores d_counts to zero. grid = NB, block = 256 (thread = position)
// ---------------------------------------------------------------------------
__global__ void build_kernel() {
    __shared__ int wcnt[8];
    int b = blockIdx.x, t = threadIdx.x;
    int warp = t >> 5, lane = t & 31;

    int cnt[KSEL]; int any = 0;
#pragma unroll
    for (int k = 0; k < KSEL; k++) {
        cnt[k] = d_counts[b][k][t];
        any |= cnt[k];
        d_counts[b][k][t] = 0;
    }
    unsigned m = __ballot_sync(0xffffffffu, any != 0);
    if (lane == 0) wcnt[warp] = __popc(m);
    __syncthreads();
    int basec = 0, ntot = 0;
#pragma unroll
    for (int wj = 0; wj < 8; wj++) {
        int wc = wcnt[wj];
        if (wj < warp) basec += wc;
        ntot += wc;
    }
    if (any) {
        int slot = basec + __popc(m & ((1u << lane) - 1u));
        d_epos[b][slot] = t;
#pragma unroll
        for (int k = 0; k < KSEL; k++) {
            float w = __fdiv_rn((float)cnt[k], 500.0f);
            uint32_t wb = __float_as_uint(w);
            d_ewt2[b][slot][k] = ((ull)wb << 32) | (ull)wb;
        }
    }
    if (t == 0) d_nentry[b] = ntot;
}

// ---------------------------------------------------------------------------
// Kernel 3: patch assembly. 16 k fused; each thread computes 2 rows x 1
// q-pair (4 pixels) so weight LDS.128 broadcasts amortize over 2 rows.
// grid = (32 ptile, 3 c, 8 b), block = 128: qt = t&63, pr = t>>6 (0..1).
// ---------------------------------------------------------------------------
__device__ __forceinline__ ull fma2(ull a, ull b, ull c) {
    ull d;
    asm("fma.rn.f32x2 %0, %1, %2, %3;" : "=l"(d) : "l"(a), "l"(b), "l"(c));
    return d;
}

__global__ void __launch_bounds__(128) assemble_kernel(const float* __restrict__ x,
                                                       float* __restrict__ out) {
    __shared__ int s_pos[DPOS];
    __shared__ alignas(16) ull s_wt2[DPOS][KSEL];

    int pt = blockIdx.x;          // 0..31
    int c  = blockIdx.y;
    int b  = blockIdx.z;
    int t  = threadIdx.x;

    int nE = d_nentry[b];
    for (int i = t; i < nE; i += 128) s_pos[i] = d_epos[b][i];
    {   // 128-bit staging of weight table
        const ulonglong2* src = (const ulonglong2*)&d_ewt2[b][0][0];
        ulonglong2* dst = (ulonglong2*)&s_wt2[0][0];
        int n2 = nE * (KSEL / 2);
        for (int i = t; i < n2; i += 128) dst[i] = src[i];
    }
    __syncthreads();

    int qt = t & 63;              // q pair: q = 2qt, 2qt+1
    int pr = t >> 6;              // 0..1
    int p0 = pt * 4 + pr * 2;     // rows p0, p0+1
    int qc = 2 * qt - 32;         // window col offset (even)
    int pc0 = p0 - 32;

    ull acc0[KSEL], acc1[KSEL];
#pragma unroll
    for (int k = 0; k < KSEL; k++) { acc0[k] = 0ull; acc1[k] = 0ull; }

    const float* xb = x + ((size_t)(b * NCH + c) << 20);

    int e = 0;
    for (; e + 2 <= nE; e += 2) {
        int posA = s_pos[e], posB = s_pos[e + 1];
        int colA = (posA & 15) * 64 + qc;
        int colB = (posB & 15) * 64 + qc;
        int rwA0 = (posA >> 4) * 64 + pc0;
        int rwB0 = (posB >> 4) * 64 + pc0;
        bool cokA = (unsigned)colA < 1024u;
        bool cokB = (unsigned)colB < 1024u;
        ull vA0 = 0ull, vA1 = 0ull, vB0 = 0ull, vB1 = 0ull;
        const float* pa = xb + ((size_t)rwA0 << 10) + colA;
        const float* pb = xb + ((size_t)rwB0 << 10) + colB;
        if (cokA && (unsigned)rwA0 < 1024u)       vA0 = *(const ull*)pa;
        if (cokA && (unsigned)(rwA0 + 1) < 1024u) vA1 = *(const ull*)(pa + IMG);
        if (cokB && (unsigned)rwB0 < 1024u)       vB0 = *(const ull*)pb;
        if (cokB && (unsigned)(rwB0 + 1) < 1024u) vB1 = *(const ull*)(pb + IMG);
#pragma unroll
        for (int j = 0; j < 8; j++) {
            ulonglong2 wA = *(const ulonglong2*)&s_wt2[e][2 * j];
            ulonglong2 wB = *(const ulonglong2*)&s_wt2[e + 1][2 * j];
            acc0[2 * j]     = fma2(wA.x, vA0, acc0[2 * j]);
            acc1[2 * j]     = fma2(wA.x, vA1, acc1[2 * j]);
            acc0[2 * j + 1] = fma2(wA.y, vA0, acc0[2 * j + 1]);
            acc1[2 * j + 1] = fma2(wA.y, vA1, acc1[2 * j + 1]);
            acc0[2 * j]     = fma2(wB.x, vB0, acc0[2 * j]);
            acc1[2 * j]     = fma2(wB.x, vB1, acc1[2 * j]);
            acc0[2 * j + 1] = fma2(wB.y, vB0, acc0[2 * j + 1]);
            acc1[2 * j + 1] = fma2(wB.y, vB1, acc1[2 * j + 1]);
        }
    }
    for (; e < nE; e++) {
        int pos = s_pos[e];
        int col = (pos & 15) * 64 + qc;
        int rw0 = (pos >> 4) * 64 + pc0;
        bool cok = (unsigned)col < 1024u;
        ull v0 = 0ull, v1 = 0ull;
        const float* pa = xb + ((size_t)rw0 << 10) + col;
        if (cok && (unsigned)rw0 < 1024u)       v0 = *(const ull*)pa;
        if (cok && (unsigned)(rw0 + 1) < 1024u) v1 = *(const ull*)(pa + IMG);
#pragma unroll
        for (int j = 0; j < 8; j++) {
            ulonglong2 w = *(const ulonglong2*)&s_wt2[e][2 * j];
            acc0[2 * j]     = fma2(w.x, v0, acc0[2 * j]);
            acc1[2 * j]     = fma2(w.x, v1, acc1[2 * j]);
            acc0[2 * j + 1] = fma2(w.y, v0, acc0[2 * j + 1]);
            acc1[2 * j + 1] = fma2(w.y, v1, acc1[2 * j + 1]);
        }
    }

#pragma unroll
    for (int k = 0; k < KSEL; k++) {
        float* op = out + (((size_t)((b * KSEL + k) * NCH + c)) << 14)
                        + ((size_t)p0 << 7) + 2 * qt;
        *(ull*)op           = acc0[k];
        *(ull*)(op + PATCH) = acc1[k];
    }
}

// ---------------------------------------------------------------------------
extern "C" void kernel_launch(void* const* d_in, const int* in_sizes, int n_in,
                              void* d_out, int out_size) {
    const float* x      = (const float*)d_in[0];
    const float* scores = (const float*)d_in[1];
    if (n_in >= 2 && in_sizes[0] == NB * HGRID * WGRID) {
        const float* tmp = x; x = scores; scores = tmp;
    }
    float* out = (float*)d_out;

    indicator_kernel<<<dim3(125, NB), 128>>>(scores);
    build_kernel<<<NB, 256>>>();
    assemble_kernel<<<dim3(32, NCH, NB), 128>>>(x, out);
}

// round 6
// speedup vs baseline: 2.6729x; 1.2573x over previous
#include <cuda_runtime.h>
#include <cstdint>

#define NB      8
#define NCH     3
#define IMG     1024
#define PATCH   128
#define DPOS    256
#define KSEL    16
#define NSAMP   500
#define HGRID   16
#define WGRID   16
#define NKB     4          // k blocks
#define KPB     4          // k per block

typedef unsigned long long ull;

// Persistent device scratch (zero-init at load; build_kernel re-zeroes
// d_counts after consuming it -> clean state for every graph replay).
__device__ int  d_counts[NB][KSEL][DPOS];
__device__ int  d_koff[NB][NKB + 1];
__device__ int  d_kpos[NB][NKB * DPOS];
__device__ __align__(32) ull d_kwt[NB][NKB * DPOS][KPB];  // packed {w,w} f32x2

// ---------------------------------------------------------------------------
// Threefry-2x32 (20 rounds), JAX partitionable layout:
//   bits[f] = o0 ^ o1 of E(key=(0,42), ctr=(hi=0, lo=f))
// ---------------------------------------------------------------------------
__device__ __forceinline__ uint32_t threefry_bits(uint32_t ctr) {
    const uint32_t K0 = 0u;
    const uint32_t K1 = 42u;
    const uint32_t K2 = 0x1BD11BDAu ^ K0 ^ K1;
    uint32_t x0 = K0;
    uint32_t x1 = ctr + K1;
#define TFR(r) { x0 += x1; x1 = __funnelshift_l(x1, x1, (r)); x1 ^= x0; }
    TFR(13) TFR(15) TFR(26) TFR(6)
    x0 += K1; x1 += K2 + 1u;
    TFR(17) TFR(29) TFR(16) TFR(24)
    x0 += K2; x1 += K0 + 2u;
    TFR(13) TFR(15) TFR(26) TFR(6)
    x0 += K0; x1 += K1 + 3u;
    TFR(17) TFR(29) TFR(16) TFR(24)
    x0 += K1; x1 += K2 + 4u;
    TFR(13) TFR(15) TFR(26) TFR(6)
    x0 += K2; x1 += K0 + 5u;
#undef TFR
    return x0 ^ x1;
}

__device__ __forceinline__ float jax_normal(uint32_t f) {
    uint32_t bits = threefry_bits(f);
    float fl = __uint_as_float((bits >> 9) | 0x3f800000u) - 1.0f;  // [0,1)
    const float lo = -0.99999994f;
    float u = fl * 2.0f + lo;
    u = fmaxf(lo, u);
    return __uint_as_float(0x3fb504f3u) * erfinvf(u);   // sqrt(2)*erfinv
}

// monotone float -> sortable u32 (strictly order-preserving)
__device__ __forceinline__ uint32_t fkey(float v) {
    uint32_t u = __float_as_uint(v);
    return u ^ (uint32_t)(((int)u >> 31) | 0x80000000);
}

// ---------------------------------------------------------------------------
// Kernel 1: perturbed top-K counting; fused normalization; 1 sample/warp,
// REDUX selection. grid = (63, NB), block = 256 (8 warps).
// ---------------------------------------------------------------------------
__global__ void __launch_bounds__(256) indicator_kernel(const float* __restrict__ scores) {
    __shared__ float s_sh[DPOS];
    __shared__ float red[64];
    int b = blockIdx.y;
    int t = threadIdx.x;
    int warp = t >> 5, lane = t & 31;

    // per-batch min/max normalize (redundant per block; trivial)
    float v0 = __ldg(scores + b * DPOS + t);   // t covers 0..255
    float mn = v0, mx = v0;
#pragma unroll
    for (int off = 16; off; off >>= 1) {
        mn = fminf(mn, __shfl_down_sync(0xffffffffu, mn, off));
        mx = fmaxf(mx, __shfl_down_sync(0xffffffffu, mx, off));
    }
    if (lane == 0) { red[warp] = mn; red[32 + warp] = mx; }
    __syncthreads();
    if (t == 0) {
        float m0 = red[0], m1 = red[32];
#pragma unroll
        for (int j = 1; j < 8; j++) { m0 = fminf(m0, red[j]); m1 = fmaxf(m1, red[32 + j]); }
        red[0] = m0; red[32] = m1;
    }
    __syncthreads();
    mn = red[0]; mx = red[32];
    float den = (mx - mn) + 1e-5f;
    s_sh[t] = __fdiv_rn(v0 - mn, den);
    __syncthreads();

    int sample = blockIdx.x * 8 + warp;            // 0..503
    bool valid = sample < NSAMP;
    uint32_t base = (uint32_t)((b * NSAMP + sample) * DPOS);

    uint32_t ka[8];
#pragma unroll
    for (int j = 0; j < 8; j++) {
        int pos = j * 32 + lane;
        float z = jax_normal(base + (uint32_t)pos);
        ka[j] = fkey(__fadd_rn(s_sh[pos], __fmul_rn(z, 0.05f)));
    }

    int sel = 0;
    for (int it = 0; it < KSEL; it++) {
        uint32_t bk = 0u;
        int bp = 0x7fffffff;
#pragma unroll
        for (int j = 0; j < 8; j++) {
            int pos = j * 32 + lane;
            if (ka[j] > bk) { bk = ka[j]; bp = pos; }
        }
        uint32_t m = __reduce_max_sync(0xffffffffu, bk);
        unsigned cand = (bk == m) ? (unsigned)bp : 0x7fffffffu;
        int w = (int)__reduce_min_sync(0xffffffffu, cand);
        int sj = w >> 5;
        if (lane == (w & 31)) {
#pragma unroll
            for (int j = 0; j < 8; j++) if (j == sj) ka[j] = 0u;
        }
        if (lane == it) sel = w;
    }

    // rank = index order among the 16 selections
    int r = 0;
#pragma unroll
    for (int j = 0; j < KSEL; j++) {
        int o = __shfl_sync(0xffffffffu, sel, j);
        if (o < sel) r++;
    }
    if (valid && lane < KSEL) atomicAdd(&d_counts[b][r][sel], 1);
}

// ---------------------------------------------------------------------------
// Kernel 2: build per-(b, kblock) sub-lists (positions with any nonzero
// count among that block's 4 ranks) + packed f32x2 weights. Re-zeroes
// d_counts. grid = NB, block = 256 (thread = position).
// ---------------------------------------------------------------------------
__global__ void build_kernel() {
    __shared__ int wcnt[8];
    __shared__ int s_base;
    int b = blockIdx.x, t = threadIdx.x;
    int warp = t >> 5, lane = t & 31;

    int cnt[KSEL];
#pragma unroll
    for (int k = 0; k < KSEL; k++) { cnt[k] = d_counts[b][k][t]; d_counts[b][k][t] = 0; }
    if (t == 0) s_base = 0;
    __syncthreads();

#pragma unroll
    for (int kb = 0; kb < NKB; kb++) {
        int any = cnt[4 * kb] | cnt[4 * kb + 1] | cnt[4 * kb + 2] | cnt[4 * kb + 3];
        unsigned m = __ballot_sync(0xffffffffu, any != 0);
        if (lane == 0) wcnt[warp] = __popc(m);
        __syncthreads();
        int basec = 0, ntot = 0;
#pragma unroll
        for (int wj = 0; wj < 8; wj++) {
            int wc = wcnt[wj];
            if (wj < warp) basec += wc;
            ntot += wc;
        }
        int base = s_base;
        if (any) {
            int slot = base + basec + __popc(m & ((1u << lane) - 1u));
            d_kpos[b][slot] = t;
#pragma unroll
            for (int j = 0; j < KPB; j++) {
                float w = __fdiv_rn((float)cnt[4 * kb + j], 500.0f);
                uint32_t wb = __float_as_uint(w);
                d_kwt[b][slot][j] = ((ull)wb << 32) | (ull)wb;
            }
        }
        if (t == 0) d_koff[b][kb] = base;
        __syncthreads();
        if (t == 0) s_base = base + ntot;
        __syncthreads();
    }
    if (t == 0) d_koff[b][NKB] = s_base;
}

// ---------------------------------------------------------------------------
// Kernel 3: patch assembly. 4 sequential k-block phases; per phase only
// 4 k accumulators (8 fma2/entry for 2 rows). Repeated window reads across
// phases hit L1. grid = (32 pt, 3 c, 8 b), block = 128.
// ---------------------------------------------------------------------------
__device__ __forceinline__ ull fma2(ull a, ull b, ull c) {
    ull d;
    asm("fma.rn.f32x2 %0, %1, %2, %3;" : "=l"(d) : "l"(a), "l"(b), "l"(c));
    return d;
}

__global__ void __launch_bounds__(128) assemble_kernel(const float* __restrict__ x,
                                                       float* __restrict__ out) {
    __shared__ int s_off[NKB + 1];
    __shared__ int s_pos[NKB * DPOS];
    __shared__ alignas(32) ull s_wt[NKB * DPOS][KPB];

    int pt = blockIdx.x;          // 0..31
    int c  = blockIdx.y;
    int b  = blockIdx.z;
    int t  = threadIdx.x;

    int ntot = d_koff[b][NKB];
    if (t <= NKB) s_off[t] = d_koff[b][t];
    for (int i = t; i < ntot; i += 128) s_pos[i] = d_kpos[b][i];
    {   // 128-bit staging of weight table
        const ulonglong2* src = (const ulonglong2*)&d_kwt[b][0][0];
        ulonglong2* dst = (ulonglong2*)&s_wt[0][0];
        int n2 = ntot * 2;
        for (int i = t; i < n2; i += 128) dst[i] = src[i];
    }
    __syncthreads();

    int qt = t & 63;              // q pair: q = 2qt, 2qt+1
    int pr = t >> 6;              // 0..1
    int p0 = pt * 4 + pr * 2;     // rows p0, p0+1
    int qc = 2 * qt - 32;         // window col offset (even)
    int pc0 = p0 - 32;

    const float* xb = x + ((size_t)(b * NCH + c) << 20);

#pragma unroll
    for (int kb = 0; kb < NKB; kb++) {
        int e    = s_off[kb];
        int eend = s_off[kb + 1];

        ull acc0[KPB], acc1[KPB];
#pragma unroll
        for (int j = 0; j < KPB; j++) { acc0[j] = 0ull; acc1[j] = 0ull; }

        for (; e + 2 <= eend; e += 2) {
            int posA = s_pos[e], posB = s_pos[e + 1];
            int colA = (posA & 15) * 64 + qc;
            int colB = (posB & 15) * 64 + qc;
            int rwA0 = (posA >> 4) * 64 + pc0;
            int rwB0 = (posB >> 4) * 64 + pc0;
            bool cokA = (unsigned)colA < 1024u;
            bool cokB = (unsigned)colB < 1024u;
            ull vA0 = 0ull, vA1 = 0ull, vB0 = 0ull, vB1 = 0ull;
            const float* pa = xb + ((size_t)rwA0 << 10) + colA;
            const float* pb = xb + ((size_t)rwB0 << 10) + colB;
            if (cokA && (unsigned)rwA0 < 1024u)       vA0 = *(const ull*)pa;
            if (cokA && (unsigned)(rwA0 + 1) < 1024u) vA1 = *(const ull*)(pa + IMG);
            if (cokB && (unsigned)rwB0 < 1024u)       vB0 = *(const ull*)pb;
            if (cokB && (unsigned)(rwB0 + 1) < 1024u) vB1 = *(const ull*)(pb + IMG);
            ulonglong2 wA0 = *(const ulonglong2*)&s_wt[e][0];
            ulonglong2 wA1 = *(const ulonglong2*)&s_wt[e][2];
            ulonglong2 wB0 = *(const ulonglong2*)&s_wt[e + 1][0];
            ulonglong2 wB1 = *(const ulonglong2*)&s_wt[e + 1][2];
            acc0[0] = fma2(wA0.x, vA0, acc0[0]); acc1[0] = fma2(wA0.x, vA1, acc1[0]);
            acc0[1] = fma2(wA0.y, vA0, acc0[1]); acc1[1] = fma2(wA0.y, vA1, acc1[1]);
            acc0[2] = fma2(wA1.x, vA0, acc0[2]); acc1[2] = fma2(wA1.x, vA1, acc1[2]);
            acc0[3] = fma2(wA1.y, vA0, acc0[3]); acc1[3] = fma2(wA1.y, vA1, acc1[3]);
            acc0[0] = fma2(wB0.x, vB0, acc0[0]); acc1[0] = fma2(wB0.x, vB1, acc1[0]);
            acc0[1] = fma2(wB0.y, vB0, acc0[1]); acc1[1] = fma2(wB0.y, vB1, acc1[1]);
            acc0[2] = fma2(wB1.x, vB0, acc0[2]); acc1[2] = fma2(wB1.x, vB1, acc1[2]);
            acc0[3] = fma2(wB1.y, vB0, acc0[3]); acc1[3] = fma2(wB1.y, vB1, acc1[3]);
        }
        for (; e < eend; e++) {
            int pos = s_pos[e];
            int col = (pos & 15) * 64 + qc;
            int rw0 = (pos >> 4) * 64 + pc0;
            bool cok = (unsigned)col < 1024u;
            ull v0 = 0ull, v1 = 0ull;
            const float* pa = xb + ((size_t)rw0 << 10) + col;
            if (cok && (unsigned)rw0 < 1024u)       v0 = *(const ull*)pa;
            if (cok && (unsigned)(rw0 + 1) < 1024u) v1 = *(const ull*)(pa + IMG);
            ulonglong2 w0 = *(const ulonglong2*)&s_wt[e][0];
            ulonglong2 w1 = *(const ulonglong2*)&s_wt[e][2];
            acc0[0] = fma2(w0.x, v0, acc0[0]); acc1[0] = fma2(w0.x, v1, acc1[0]);
            acc0[1] = fma2(w0.y, v0, acc0[1]); acc1[1] = fma2(w0.y, v1, acc1[1]);
            acc0[2] = fma2(w1.x, v0, acc0[2]); acc1[2] = fma2(w1.x, v1, acc1[2]);
            acc0[3] = fma2(w1.y, v0, acc0[3]); acc1[3] = fma2(w1.y, v1, acc1[3]);
        }

#pragma unroll
        for (int j = 0; j < KPB; j++) {
            int k = kb * KPB + j;
            float* op = out + (((size_t)((b * KSEL + k) * NCH + c)) << 14)
                            + ((size_t)p0 << 7) + 2 * qt;
            *(ull*)op           = acc0[j];
            *(ull*)(op + PATCH) = acc1[j];
        }
    }
}

// ---------------------------------------------------------------------------
extern "C" void kernel_launch(void* const* d_in, const int* in_sizes, int n_in,
                              void* d_out, int out_size) {
    const float* x      = (const float*)d_in[0];
    const float* scores = (const float*)d_in[1];
    if (n_in >= 2 && in_sizes[0] == NB * HGRID * WGRID) {
        const float* tmp = x; x = scores; scores = tmp;
    }
    float* out = (float*)d_out;

    indicator_kernel<<<dim3(63, NB), 256>>>(scores);
    build_kernel<<<NB, 256>>>();
    assemble_kernel<<<dim3(32, NCH, NB), 128>>>(x, out);
}